// round 1
// baseline (speedup 1.0000x reference)
#include <cuda_runtime.h>
#include <math.h>

#define BATCH  4
#define SEQ    2048
#define DIM    512
#define HEADS  8
#define DHEAD  64
#define INNER  512          // HEADS*DHEAD
#define TRIPLE 1536         // 3*INNER
#define ROWS   (BATCH * SEQ)   // 8192

// ---------------- scratch (device globals; no runtime allocation) ----------
__device__ float g_xn[ROWS * DIM];                    // layernormed x   [8192,512]
__device__ float g_q [BATCH * HEADS * SEQ * DHEAD];   // [b,h,n,dh]
__device__ float g_k [BATCH * HEADS * SEQ * DHEAD];
__device__ float g_v [BATCH * HEADS * SEQ * DHEAD];
__device__ float g_ao[ROWS * INNER];                  // attention out [b,n,h*dh]

// ---------------------------------------------------------------- LayerNorm
__global__ __launch_bounds__(128)
void ln_kernel(const float* __restrict__ x,
               const float* __restrict__ gamma,
               const float* __restrict__ beta) {
    const int row = blockIdx.x;          // 0..8191
    const int t   = threadIdx.x;         // 0..127, 4 floats each
    float4 v = ((const float4*)(x + (size_t)row * DIM))[t];
    float s  = v.x + v.y + v.z + v.w;
    float ss = v.x*v.x + v.y*v.y + v.z*v.z + v.w*v.w;
    #pragma unroll
    for (int o = 16; o > 0; o >>= 1) {
        s  += __shfl_xor_sync(0xffffffffu, s,  o);
        ss += __shfl_xor_sync(0xffffffffu, ss, o);
    }
    __shared__ float sh_s[4], sh_ss[4];
    const int w = t >> 5;
    if ((t & 31) == 0) { sh_s[w] = s; sh_ss[w] = ss; }
    __syncthreads();
    s  = sh_s[0] + sh_s[1] + sh_s[2] + sh_s[3];
    ss = sh_ss[0] + sh_ss[1] + sh_ss[2] + sh_ss[3];
    const float mu  = s * (1.0f / DIM);
    const float var = ss * (1.0f / DIM) - mu * mu;
    const float inv = rsqrtf(var + 1e-5f);
    float4 g  = ((const float4*)gamma)[t];
    float4 be = ((const float4*)beta)[t];
    float4 o;
    o.x = (v.x - mu) * inv * g.x + be.x;
    o.y = (v.y - mu) * inv * g.y + be.y;
    o.z = (v.z - mu) * inv * g.z + be.z;
    o.w = (v.w - mu) * inv * g.w + be.w;
    ((float4*)(g_xn + (size_t)row * DIM))[t] = o;
}

// -------------------------------------------- tiled SGEMM 128x128x8, 8x8/thr
// QKV_SCATTER=true : A = g_xn, epilogue scatters into g_q/g_k/g_v head layout
// QKV_SCATTER=false: A = g_ao, epilogue writes C row-major
template<int NOUT, bool QKV_SCATTER>
__global__ __launch_bounds__(256, 2)
void sgemm_kernel(const float* __restrict__ W, float* __restrict__ C) {
    constexpr int K = 512;
    __shared__ float As[8][128];
    __shared__ float Bs[8][128];

    const float* A = QKV_SCATTER ? g_xn : g_ao;

    const int tid = threadIdx.x;
    const int bm  = blockIdx.y * 128;
    const int bn  = blockIdx.x * 128;
    const int ty  = tid >> 4;
    const int tx  = tid & 15;
    const int lm  = tid >> 1;             // 0..127 (A row within tile)
    const int lk4 = (tid & 1) << 2;       // 0 or 4
    const int lbk = tid >> 5;             // 0..7
    const int lbn = (tid & 31) << 2;      // 0..124

    float acc[8][8];
    #pragma unroll
    for (int i = 0; i < 8; ++i)
        #pragma unroll
        for (int j = 0; j < 8; ++j) acc[i][j] = 0.f;

    const float* Aptr = A + (size_t)(bm + lm) * K + lk4;
    const float* Wptr = W + (size_t)lbk * NOUT + bn + lbn;

    for (int k0 = 0; k0 < K; k0 += 8) {
        float4 av = *(const float4*)(Aptr + k0);
        As[lk4 + 0][lm] = av.x;
        As[lk4 + 1][lm] = av.y;
        As[lk4 + 2][lm] = av.z;
        As[lk4 + 3][lm] = av.w;
        *(float4*)(&Bs[lbk][lbn]) = *(const float4*)(Wptr + (size_t)k0 * NOUT);
        __syncthreads();
        #pragma unroll
        for (int k = 0; k < 8; ++k) {
            float a[8], b[8];
            *(float4*)(a)     = *(const float4*)(&As[k][ty * 8]);
            *(float4*)(a + 4) = *(const float4*)(&As[k][ty * 8 + 4]);
            *(float4*)(b)     = *(const float4*)(&Bs[k][tx * 8]);
            *(float4*)(b + 4) = *(const float4*)(&Bs[k][tx * 8 + 4]);
            #pragma unroll
            for (int i = 0; i < 8; ++i)
                #pragma unroll
                for (int j = 0; j < 8; ++j)
                    acc[i][j] = fmaf(a[i], b[j], acc[i][j]);
        }
        __syncthreads();
    }

    if (QKV_SCATTER) {
        #pragma unroll
        for (int i = 0; i < 8; ++i) {
            const int row = bm + ty * 8 + i;
            const int bb  = row >> 11;      // /SEQ
            const int nn  = row & 2047;
            #pragma unroll
            for (int j = 0; j < 8; ++j) {
                const int col  = bn + tx * 8 + j;
                const int part = col >> 9;      // 0=q 1=k 2=v
                const int rem  = col & 511;
                const int h    = rem >> 6;
                const int d    = rem & 63;
                float* dst = (part == 0) ? g_q : (part == 1 ? g_k : g_v);
                dst[(((size_t)(bb * HEADS + h)) * SEQ + nn) * DHEAD + d] = acc[i][j];
            }
        }
    } else {
        #pragma unroll
        for (int i = 0; i < 8; ++i) {
            const int row = bm + ty * 8 + i;
            float4 c0, c1;
            c0.x = acc[i][0]; c0.y = acc[i][1]; c0.z = acc[i][2]; c0.w = acc[i][3];
            c1.x = acc[i][4]; c1.y = acc[i][5]; c1.z = acc[i][6]; c1.w = acc[i][7];
            *(float4*)(C + (size_t)row * NOUT + bn + tx * 8)     = c0;
            *(float4*)(C + (size_t)row * NOUT + bn + tx * 8 + 4) = c1;
        }
    }
}

// ------------------------------------------------- flash-style attention
// One block = 64 queries of one (b,h). 256 threads as 16x16, 4x4 micro-tiles.
// Static smem exactly 48KB: Qs + (Ks overlaid with Ps) + Vs, each 64x64 f32.
__global__ __launch_bounds__(256, 2)
void attn_kernel(const float* __restrict__ pose_bias,
                 const float* __restrict__ beta_ptr) {
    __shared__ float Qs [64 * 64];   // Qs[d*64 + q]   (d-major)
    __shared__ float KPs[64 * 64];   // Ks[d*64 + j], later Ps[j*64 + q]
    __shared__ float Vs [64 * 64];   // Vs[j*64 + d]

    const int tid = threadIdx.x;
    const int ty  = tid >> 4;
    const int tx  = tid & 15;
    const int q0  = blockIdx.x * 64;
    const int bh  = blockIdx.y;
    const int b   = bh >> 3;
    const int h   = bh & 7;

    const float bet   = *beta_ptr;
    const float scale = 0.125f;   // DHEAD^-0.5

    // Q tile -> smem transposed
    const float* qbase = g_q + ((size_t)bh * SEQ + q0) * DHEAD;
    #pragma unroll
    for (int r = 0; r < 4; ++r) {
        int idx = tid + r * 256;
        int qq  = idx >> 4;
        int d4  = (idx & 15) << 2;
        float4 v = *(const float4*)(qbase + qq * DHEAD + d4);
        Qs[(d4 + 0) * 64 + qq] = v.x;
        Qs[(d4 + 1) * 64 + qq] = v.y;
        Qs[(d4 + 2) * 64 + qq] = v.z;
        Qs[(d4 + 3) * 64 + qq] = v.w;
    }
    // per-thread query-row pose bias (constant over key tiles)
    float bq[4];
    #pragma unroll
    for (int i = 0; i < 4; ++i)
        bq[i] = bet * __ldg(&pose_bias[(size_t)b * SEQ + q0 + ty * 4 + i]);

    float m_run[4], l_run[4], o[4][4];
    #pragma unroll
    for (int i = 0; i < 4; ++i) {
        m_run[i] = -INFINITY;
        l_run[i] = 0.f;
        #pragma unroll
        for (int j = 0; j < 4; ++j) o[i][j] = 0.f;
    }

    const float* kbase = g_k + (size_t)bh * SEQ * DHEAD;
    const float* vbase = g_v + (size_t)bh * SEQ * DHEAD;

    for (int j0 = 0; j0 < SEQ; j0 += 64) {
        __syncthreads();   // previous PV done before overwriting Ks/Vs
        #pragma unroll
        for (int r = 0; r < 4; ++r) {
            int idx = tid + r * 256;
            int jj  = idx >> 4;
            int d4  = (idx & 15) << 2;
            float4 kv = *(const float4*)(kbase + (size_t)(j0 + jj) * DHEAD + d4);
            KPs[(d4 + 0) * 64 + jj] = kv.x;
            KPs[(d4 + 1) * 64 + jj] = kv.y;
            KPs[(d4 + 2) * 64 + jj] = kv.z;
            KPs[(d4 + 3) * 64 + jj] = kv.w;
            *(float4*)(&Vs[jj * 64 + d4]) =
                *(const float4*)(vbase + (size_t)(j0 + jj) * DHEAD + d4);
        }
        __syncthreads();

        // S = Q @ K^T  (contract over d)
        float s[4][4];
        #pragma unroll
        for (int i = 0; i < 4; ++i)
            #pragma unroll
            for (int j = 0; j < 4; ++j) s[i][j] = 0.f;
        #pragma unroll 8
        for (int d = 0; d < 64; ++d) {
            float4 qa = *(const float4*)(&Qs [d * 64 + ty * 4]);
            float4 kb = *(const float4*)(&KPs[d * 64 + tx * 4]);
            float ar[4] = {qa.x, qa.y, qa.z, qa.w};
            float br[4] = {kb.x, kb.y, kb.z, kb.w};
            #pragma unroll
            for (int i = 0; i < 4; ++i)
                #pragma unroll
                for (int j = 0; j < 4; ++j)
                    s[i][j] = fmaf(ar[i], br[j], s[i][j]);
        }
        __syncthreads();   // everyone done reading Ks before P overwrites it

        // key-column pose bias for this tile
        float bk[4];
        #pragma unroll
        for (int j = 0; j < 4; ++j)
            bk[j] = bet * __ldg(&pose_bias[(size_t)b * SEQ + j0 + tx * 4 + j]);

        // online softmax per query row; lanes with equal ty share rows
        #pragma unroll
        for (int i = 0; i < 4; ++i) {
            float sv[4];
            #pragma unroll
            for (int j = 0; j < 4; ++j)
                sv[j] = s[i][j] * scale + bq[i] + bk[j];
            float tmax = fmaxf(fmaxf(sv[0], sv[1]), fmaxf(sv[2], sv[3]));
            #pragma unroll
            for (int off = 1; off <= 8; off <<= 1)
                tmax = fmaxf(tmax, __shfl_xor_sync(0xffffffffu, tmax, off));
            const float m_new = fmaxf(m_run[i], tmax);
            const float corr  = __expf(m_run[i] - m_new);
            m_run[i] = m_new;
            float tsum = 0.f;
            #pragma unroll
            for (int j = 0; j < 4; ++j) {
                sv[j] = __expf(sv[j] - m_new);
                tsum += sv[j];
            }
            #pragma unroll
            for (int off = 1; off <= 8; off <<= 1)
                tsum += __shfl_xor_sync(0xffffffffu, tsum, off);
            l_run[i] = l_run[i] * corr + tsum;
            #pragma unroll
            for (int j = 0; j < 4; ++j) {
                o[i][j] *= corr;
                KPs[(tx * 4 + j) * 64 + ty * 4 + i] = sv[j];   // Ps[j][q]
            }
        }
        __syncthreads();

        // O += P @ V (contract over keys)
        #pragma unroll 8
        for (int jj = 0; jj < 64; ++jj) {
            float4 pa = *(const float4*)(&KPs[jj * 64 + ty * 4]);
            float4 vb = *(const float4*)(&Vs [jj * 64 + tx * 4]);
            float ar[4] = {pa.x, pa.y, pa.z, pa.w};
            float br[4] = {vb.x, vb.y, vb.z, vb.w};
            #pragma unroll
            for (int i = 0; i < 4; ++i)
                #pragma unroll
                for (int j = 0; j < 4; ++j)
                    o[i][j] = fmaf(ar[i], br[j], o[i][j]);
        }
    }

    // normalize + store to [b,n,h*dh]
    float* aobase = g_ao + ((size_t)(b * SEQ + q0)) * INNER + h * 64;
    #pragma unroll
    for (int i = 0; i < 4; ++i) {
        const float inv = 1.0f / l_run[i];
        float4 w;
        w.x = o[i][0] * inv; w.y = o[i][1] * inv;
        w.z = o[i][2] * inv; w.w = o[i][3] * inv;
        *(float4*)(aobase + (size_t)(ty * 4 + i) * INNER + tx * 4) = w;
    }
}

// --------------------------------------------------------------- launcher
extern "C" void kernel_launch(void* const* d_in, const int* in_sizes, int n_in,
                              void* d_out, int out_size) {
    const float* x         = (const float*)d_in[0];
    const float* pose_bias = (const float*)d_in[1];
    const float* ln_gamma  = (const float*)d_in[2];
    const float* ln_beta   = (const float*)d_in[3];
    const float* w_qkv     = (const float*)d_in[4];
    const float* w_out     = (const float*)d_in[5];
    const float* beta      = (const float*)d_in[6];
    float* out = (float*)d_out;

    // 1) LayerNorm
    ln_kernel<<<ROWS, 128>>>(x, ln_gamma, ln_beta);

    // 2) QKV projection, scattered into head layout
    sgemm_kernel<TRIPLE, true><<<dim3(TRIPLE / 128, ROWS / 128), 256>>>(w_qkv, nullptr);

    // 3) attention (flash-style, online softmax)
    attn_kernel<<<dim3(SEQ / 64, BATCH * HEADS), 256>>>(pose_bias, beta);

    // 4) output projection
    sgemm_kernel<INNER, false><<<dim3(INNER / 128, ROWS / 128), 256>>>(w_out, out);
}

// round 2
// speedup vs baseline: 1.2935x; 1.2935x over previous
#include <cuda_runtime.h>
#include <math.h>

#define BATCH  4
#define SEQ    2048
#define DIM    512
#define HEADS  8
#define DHEAD  64
#define INNER  512
#define TRIPLE 1536
#define ROWS   (BATCH * SEQ)

typedef unsigned long long u64;

// ---------------- scratch (device globals) ----------------
__device__ float g_xn[ROWS * DIM];                    // layernormed x
__device__ float g_q [BATCH * HEADS * DHEAD * SEQ];   // [b,h,dh,n]  (d-major!)
__device__ float g_k [BATCH * HEADS * DHEAD * SEQ];   // [b,h,dh,n]  (d-major!)
__device__ float g_v [BATCH * HEADS * SEQ * DHEAD];   // [b,h,n,dh]
__device__ float g_ao[ROWS * INNER];                  // attention out [b,n,h*dh]

// ---------------- f32x2 helpers ----------------
__device__ __forceinline__ u64 f2_dup(float x) {
    u64 r; unsigned int u = __float_as_uint(x);
    asm("mov.b64 %0, {%1, %2};" : "=l"(r) : "r"(u), "r"(u));
    return r;
}
__device__ __forceinline__ void f2_fma(u64& d, u64 a, u64 b) {
    asm("fma.rn.f32x2 %0, %1, %2, %0;" : "+l"(d) : "l"(a), "l"(b));
}
__device__ __forceinline__ void f2_mul(u64& d, u64 a) {
    asm("mul.rn.f32x2 %0, %0, %1;" : "+l"(d) : "l"(a));
}
__device__ __forceinline__ float2 f2_unpack(u64 v) {
    unsigned int lo, hi;
    asm("mov.b64 {%0, %1}, %2;" : "=r"(lo), "=r"(hi) : "l"(v));
    return make_float2(__uint_as_float(lo), __uint_as_float(hi));
}

// ---------------------------------------------------------------- LayerNorm
__global__ __launch_bounds__(128)
void ln_kernel(const float* __restrict__ x,
               const float* __restrict__ gamma,
               const float* __restrict__ beta) {
    const int row = blockIdx.x;
    const int t   = threadIdx.x;
    float4 v = ((const float4*)(x + (size_t)row * DIM))[t];
    float s  = v.x + v.y + v.z + v.w;
    float ss = v.x*v.x + v.y*v.y + v.z*v.z + v.w*v.w;
    #pragma unroll
    for (int o = 16; o > 0; o >>= 1) {
        s  += __shfl_xor_sync(0xffffffffu, s,  o);
        ss += __shfl_xor_sync(0xffffffffu, ss, o);
    }
    __shared__ float sh_s[4], sh_ss[4];
    const int w = t >> 5;
    if ((t & 31) == 0) { sh_s[w] = s; sh_ss[w] = ss; }
    __syncthreads();
    s  = sh_s[0] + sh_s[1] + sh_s[2] + sh_s[3];
    ss = sh_ss[0] + sh_ss[1] + sh_ss[2] + sh_ss[3];
    const float mu  = s * (1.0f / DIM);
    const float var = ss * (1.0f / DIM) - mu * mu;
    const float inv = rsqrtf(var + 1e-5f);
    float4 g  = ((const float4*)gamma)[t];
    float4 be = ((const float4*)beta)[t];
    float4 o;
    o.x = (v.x - mu) * inv * g.x + be.x;
    o.y = (v.y - mu) * inv * g.y + be.y;
    o.z = (v.z - mu) * inv * g.z + be.z;
    o.w = (v.w - mu) * inv * g.w + be.w;
    ((float4*)(g_xn + (size_t)row * DIM))[t] = o;
}

// -------------------------------------------- f32x2 SGEMM 128x128, K-paired
// acc2[i][j] holds (sum over even k, sum over odd k); final = lo+hi.
// Register tile strided: rows ty + 16*i, cols tx + 16*j.
template<int NOUT, bool QKV_SCATTER>
__global__ __launch_bounds__(256, 1)
void sgemm2_kernel(const float* __restrict__ W, float* __restrict__ C) {
    constexpr int K = 512;
    __shared__ __align__(16) float2 As2[4][128];   // [kpair][m] = (A[m][2kk],A[m][2kk+1])
    __shared__ __align__(16) float2 Bs2[4][128];   // [kpair][n] = (B[2kk][n],B[2kk+1][n])

    const float* A = QKV_SCATTER ? g_xn : g_ao;

    const int tid = threadIdx.x;
    const int bm  = blockIdx.y * 128;
    const int bn  = blockIdx.x * 128;
    const int ty  = tid >> 4;
    const int tx  = tid & 15;
    const int lm  = tid >> 1;               // A row in tile
    const int lk4 = (tid & 1) << 2;         // 0 or 4
    const int br  = tid >> 6;               // 0..3 : k-pair row
    const int bn2 = (tid & 63) << 1;        // 0..126 : col pair base

    u64 acc2[8][8];
    #pragma unroll
    for (int i = 0; i < 8; ++i)
        #pragma unroll
        for (int j = 0; j < 8; ++j) acc2[i][j] = 0ull;

    const float* Aptr = A + (size_t)(bm + lm) * K + lk4;
    const float* Wptr = W + (size_t)(2 * br) * NOUT + bn + bn2;

    float4 pA  = *(const float4*)(Aptr);
    float2 pB0 = *(const float2*)(Wptr);
    float2 pB1 = *(const float2*)(Wptr + NOUT);

    for (int k0 = 0; k0 < K; k0 += 8) {
        const int kk0 = lk4 >> 1;           // 0 or 2
        As2[kk0    ][lm] = make_float2(pA.x, pA.y);
        As2[kk0 + 1][lm] = make_float2(pA.z, pA.w);
        Bs2[br][bn2    ] = make_float2(pB0.x, pB1.x);
        Bs2[br][bn2 + 1] = make_float2(pB0.y, pB1.y);
        __syncthreads();

        if (k0 + 8 < K) {
            pA  = *(const float4*)(Aptr + k0 + 8);
            pB0 = *(const float2*)(Wptr + (size_t)(k0 + 8) * NOUT);
            pB1 = *(const float2*)(Wptr + (size_t)(k0 + 9) * NOUT);
        }

        #pragma unroll
        for (int kk = 0; kk < 4; ++kk) {
            u64 a2[8], b2[8];
            #pragma unroll
            for (int i = 0; i < 8; ++i)
                a2[i] = *reinterpret_cast<const u64*>(&As2[kk][ty + 16 * i]);
            #pragma unroll
            for (int j = 0; j < 8; ++j)
                b2[j] = *reinterpret_cast<const u64*>(&Bs2[kk][tx + 16 * j]);
            #pragma unroll
            for (int i = 0; i < 8; ++i)
                #pragma unroll
                for (int j = 0; j < 8; ++j)
                    f2_fma(acc2[i][j], a2[i], b2[j]);
        }
        __syncthreads();
    }

    if (QKV_SCATTER) {
        #pragma unroll
        for (int i = 0; i < 8; ++i) {
            const int row = bm + ty + 16 * i;
            const int bb  = row >> 11;
            const int nn  = row & 2047;
            #pragma unroll
            for (int j = 0; j < 8; ++j) {
                const int col  = bn + tx + 16 * j;
                const int part = col >> 9;
                const int rem  = col & 511;
                const int h    = rem >> 6;
                const int d    = rem & 63;
                float2 p = f2_unpack(acc2[i][j]);
                const float val = p.x + p.y;
                if (part == 2) {
                    g_v[(((size_t)(bb * HEADS + h)) * SEQ + nn) * DHEAD + d] = val;
                } else {
                    float* dst = (part == 0) ? g_q : g_k;
                    dst[(((size_t)(bb * HEADS + h)) * DHEAD + d) * SEQ + nn] = val;
                }
            }
        }
    } else {
        #pragma unroll
        for (int i = 0; i < 8; ++i) {
            const int row = bm + ty + 16 * i;
            #pragma unroll
            for (int j = 0; j < 8; ++j) {
                float2 p = f2_unpack(acc2[i][j]);
                C[(size_t)row * NOUT + bn + tx + 16 * j] = p.x + p.y;
            }
        }
    }
}

// ------------------------------------------------- flash attention, f32x2
// Block: 128 threads, 64 queries x 64 keys per tile.
// Thread microtile: 4 q-rows (ty+16i) x 8 k-cols as 4 adjacent pairs
// (cols 2*(tx+8*j2) +{0,1}).  Q/K in d-major global layout -> plain copies.
__global__ __launch_bounds__(128)
void attn2_kernel(const float* __restrict__ pose_bias,
                  const float* __restrict__ beta_ptr) {
    __shared__ __align__(16) float Qs [64 * 64];   // [d][q]
    __shared__ __align__(16) float KPs[64 * 64];   // K: [d][j]; later P: [k][q]
    __shared__ __align__(16) float Vs [64 * 64];   // [j][d]

    const int tid = threadIdx.x;
    const int ty  = tid >> 3;      // 0..15
    const int tx  = tid & 7;       // 0..7
    const int q0  = blockIdx.x * 64;
    const int bh  = blockIdx.y;
    const int b   = bh >> 3;
    const int h   = bh & 7;

    const float bet   = *beta_ptr;
    const float scale = 0.125f;

    // load Q tile (d-major rows, straight copy)
    const float* qg = g_q + (size_t)bh * DHEAD * SEQ + q0;
    #pragma unroll
    for (int r = 0; r < 8; ++r) {
        int idx = tid + r * 128;
        int d   = idx >> 4;
        int c4  = (idx & 15) << 2;
        *(float4*)(&Qs[d * 64 + c4]) = *(const float4*)(qg + (size_t)d * SEQ + c4);
    }

    float bq[4];
    #pragma unroll
    for (int i = 0; i < 4; ++i)
        bq[i] = bet * __ldg(&pose_bias[(size_t)b * SEQ + q0 + ty + 16 * i]);

    float m_run[4], l_run[4];
    u64 o2[4][4];
    #pragma unroll
    for (int i = 0; i < 4; ++i) {
        m_run[i] = -INFINITY; l_run[i] = 0.f;
        #pragma unroll
        for (int j = 0; j < 4; ++j) o2[i][j] = 0ull;
    }

    const float* kg = g_k + (size_t)bh * DHEAD * SEQ;
    const float* vg = g_v + (size_t)bh * SEQ * DHEAD;

    for (int j0 = 0; j0 < SEQ; j0 += 64) {
        __syncthreads();   // prev PV done (and Q store visible on first iter)
        #pragma unroll
        for (int r = 0; r < 8; ++r) {
            int idx = tid + r * 128;
            int a   = idx >> 4;
            int c4  = (idx & 15) << 2;
            *(float4*)(&KPs[a * 64 + c4]) =
                *(const float4*)(kg + (size_t)a * SEQ + j0 + c4);
            *(float4*)(&Vs[a * 64 + c4]) =
                *(const float4*)(vg + (size_t)(j0 + a) * DHEAD + c4);
        }
        __syncthreads();

        // S = Q K^T : pairs over key columns
        u64 s2[4][4];
        #pragma unroll
        for (int i = 0; i < 4; ++i)
            #pragma unroll
            for (int j = 0; j < 4; ++j) s2[i][j] = 0ull;

        #pragma unroll 4
        for (int d = 0; d < 64; ++d) {
            u64 qp[4], kb[4];
            #pragma unroll
            for (int i = 0; i < 4; ++i)
                qp[i] = f2_dup(Qs[d * 64 + ty + 16 * i]);
            #pragma unroll
            for (int j = 0; j < 4; ++j)
                kb[j] = *reinterpret_cast<const u64*>(&KPs[d * 64 + 2 * (tx + 8 * j)]);
            #pragma unroll
            for (int i = 0; i < 4; ++i)
                #pragma unroll
                for (int j = 0; j < 4; ++j)
                    f2_fma(s2[i][j], qp[i], kb[j]);
        }
        __syncthreads();   // done reading K before P overwrites

        // key-column pose bias
        float2 bk[4];
        #pragma unroll
        for (int j = 0; j < 4; ++j) {
            float2 pb = *(const float2*)(&pose_bias[(size_t)b * SEQ + j0 + 2 * (tx + 8 * j)]);
            bk[j] = make_float2(bet * pb.x, bet * pb.y);
        }

        // online softmax (rows reduced over tx: shfl 1,2,4)
        #pragma unroll
        for (int i = 0; i < 4; ++i) {
            float sv[8];
            #pragma unroll
            for (int j = 0; j < 4; ++j) {
                float2 p = f2_unpack(s2[i][j]);
                sv[2 * j]     = p.x * scale + bq[i] + bk[j].x;
                sv[2 * j + 1] = p.y * scale + bq[i] + bk[j].y;
            }
            float tmax = sv[0];
            #pragma unroll
            for (int c = 1; c < 8; ++c) tmax = fmaxf(tmax, sv[c]);
            #pragma unroll
            for (int off = 1; off <= 4; off <<= 1)
                tmax = fmaxf(tmax, __shfl_xor_sync(0xffffffffu, tmax, off));
            const float m_new = fmaxf(m_run[i], tmax);
            const float corr  = __expf(m_run[i] - m_new);
            m_run[i] = m_new;
            float tsum = 0.f;
            #pragma unroll
            for (int c = 0; c < 8; ++c) {
                sv[c] = __expf(sv[c] - m_new);
                tsum += sv[c];
            }
            #pragma unroll
            for (int off = 1; off <= 4; off <<= 1)
                tsum += __shfl_xor_sync(0xffffffffu, tsum, off);
            l_run[i] = l_run[i] * corr + tsum;
            const u64 cd = f2_dup(corr);
            #pragma unroll
            for (int j = 0; j < 4; ++j) {
                f2_mul(o2[i][j], cd);
                KPs[(2 * (tx + 8 * j))     * 64 + ty + 16 * i] = sv[2 * j];
                KPs[(2 * (tx + 8 * j) + 1) * 64 + ty + 16 * i] = sv[2 * j + 1];
            }
        }
        __syncthreads();

        // O += P V : pairs over dh columns
        #pragma unroll 4
        for (int jj = 0; jj < 64; ++jj) {
            u64 pp[4], vb[4];
            #pragma unroll
            for (int i = 0; i < 4; ++i)
                pp[i] = f2_dup(KPs[jj * 64 + ty + 16 * i]);
            #pragma unroll
            for (int j = 0; j < 4; ++j)
                vb[j] = *reinterpret_cast<const u64*>(&Vs[jj * 64 + 2 * (tx + 8 * j)]);
            #pragma unroll
            for (int i = 0; i < 4; ++i)
                #pragma unroll
                for (int j = 0; j < 4; ++j)
                    f2_fma(o2[i][j], pp[i], vb[j]);
        }
    }

    // normalize + store [b, n, h*64 + c]
    float* aobase = g_ao + ((size_t)(b * SEQ + q0)) * INNER + h * 64;
    #pragma unroll
    for (int i = 0; i < 4; ++i) {
        const float inv = 1.0f / l_run[i];
        #pragma unroll
        for (int j = 0; j < 4; ++j) {
            float2 p = f2_unpack(o2[i][j]);
            p.x *= inv; p.y *= inv;
            *(float2*)(aobase + (size_t)(ty + 16 * i) * INNER + 2 * (tx + 8 * j)) = p;
        }
    }
}

// --------------------------------------------------------------- launcher
extern "C" void kernel_launch(void* const* d_in, const int* in_sizes, int n_in,
                              void* d_out, int out_size) {
    const float* x         = (const float*)d_in[0];
    const float* pose_bias = (const float*)d_in[1];
    const float* ln_gamma  = (const float*)d_in[2];
    const float* ln_beta   = (const float*)d_in[3];
    const float* w_qkv     = (const float*)d_in[4];
    const float* w_out     = (const float*)d_in[5];
    const float* beta      = (const float*)d_in[6];
    float* out = (float*)d_out;

    ln_kernel<<<ROWS, 128>>>(x, ln_gamma, ln_beta);
    sgemm2_kernel<TRIPLE, true><<<dim3(TRIPLE / 128, ROWS / 128), 256>>>(w_qkv, nullptr);
    attn2_kernel<<<dim3(SEQ / 64, BATCH * HEADS), 128>>>(pose_bias, beta);
    sgemm2_kernel<INNER, false><<<dim3(INNER / 128, ROWS / 128), 256>>>(w_out, out);
}